// round 7
// baseline (speedup 1.0000x reference)
#include <cuda_runtime.h>
#include <cuda_bf16.h>
#include <cstdint>

#define N_TOTAL 8388608   // 2^23

__device__ float2 g_scratch[N_TOTAL];   // transposed intermediate after k1

__host__ __device__ __forceinline__ constexpr int brev_c(int x, int K) {
    int r = 0;
    for (int b = 0; b < K; b++) r |= ((x >> b) & 1) << (K - 1 - b);
    return r;
}

__device__ __forceinline__ float2 cmul(float2 a, float2 w) {
    return make_float2(a.x * w.x - a.y * w.y, a.x * w.y + a.y * w.x);
}

// butterfly network, twiddles loaded from gmem with up-front prefetch
template <int S0, int K>
__device__ __forceinline__ void bnet_pf(float2* a, unsigned jj,
                                        const float2* __restrict__ W) {
    float2 tw[(1 << K) - 1];
#pragma unroll
    for (int u = 0; u < K; u++) {
#pragma unroll
        for (int c = 0; c < (1 << u); c++) {
            unsigned idx = (jj << (22 - S0 - u)) + ((unsigned)c << (22 - u));
            tw[(1 << u) - 1 + c] = __ldg(&W[idx]);
        }
    }
#pragma unroll
    for (int u = 0; u < K; u++) {
        const int half = 1 << (K - 1 - u);
#pragma unroll
        for (int t = 0; t < (1 << K) / 2; t++) {
            const int q1 = ((t & ~(half - 1)) << 1) | (t & (half - 1));
            const int q2 = q1 + half;
            const int c = brev_c(q1, K) & ((1 << u) - 1);
            float2 w = tw[(1 << u) - 1 + c];
            float2 p = cmul(a[q2], w);
            float2 tt = a[q1];
            a[q1] = make_float2(tt.x + p.x, tt.y + p.y);
            a[q2] = make_float2(tt.x - p.x, tt.y - p.y);
        }
    }
}

// butterfly network, twiddles read from smem: tws[slot*STRIDE], slot=2^u-1+c
template <int K, int STRIDE>
__device__ __forceinline__ void bnet_tw(float2* a, const float2* tws) {
#pragma unroll
    for (int u = 0; u < K; u++) {
        const int half = 1 << (K - 1 - u);
#pragma unroll
        for (int t = 0; t < (1 << K) / 2; t++) {
            const int q1 = ((t & ~(half - 1)) << 1) | (t & (half - 1));
            const int q2 = q1 + half;
            const int c = brev_c(q1, K) & ((1 << u) - 1);
            float2 w = tws[((1 << u) - 1 + c) * STRIDE];
            float2 p = cmul(a[q2], w);
            float2 tt = a[q1];
            a[q1] = make_float2(tt.x + p.x, tt.y + p.y);
            a[q2] = make_float2(tt.x - p.x, tt.y - p.y);
        }
    }
}

// ============================================================================
// k1: stages [0,11). Tile = 8 bases x 2048 q, rounds 4+4+3.
// R2/R3 twiddles staged in smem (footprints 240 / 1792 entries per block).
// Output transposed: Yt[brev11(q)*4096 + base].
// ============================================================================
#define K1_DATA 16384
#define K1_SMEM_BYTES ((K1_DATA + 240 + 1792) * 8)

__device__ __forceinline__ unsigned phA(unsigned q, unsigned g) {
    unsigned l = (q << 3) | g;
    return l ^ (((l >> 6) & 1u) << 3);
}

__global__ void __launch_bounds__(512, 1)
fft_k1(const float* __restrict__ Xr, const float2* __restrict__ W,
       float2* __restrict__ Yt) {
    extern __shared__ float2 sm2[];
    float2* tw2 = sm2 + K1_DATA;         // [slot*16 + jj], 15x16
    float2* tw3 = sm2 + K1_DATA + 240;   // [slot*256 + (jj^(jj>>4))], 7x256

    const unsigned t = threadIdx.x;
    const unsigned g = t & 7u;
    const unsigned rest = t >> 3;        // 0..63
    const unsigned base = blockIdx.x * 8u + g;

    // cooperative twiddle staging (R2: S0=4 -> shift 18-u; R3: S0=8 -> 14-u)
    for (unsigned e = t; e < 240; e += 512) {
        unsigned slot = e >> 4, jj = e & 15u;
        unsigned u = 31 - __clz(slot + 1);
        unsigned c = slot + 1 - (1u << u);
        tw2[e] = __ldg(&W[(jj << (18 - u)) + (c << (22 - u))]);
    }
    for (unsigned e = t; e < 1792; e += 512) {
        unsigned slot = e >> 8, jj = e & 255u;
        unsigned u = 31 - __clz(slot + 1);
        unsigned c = slot + 1 - (1u << u);
        unsigned phys = (slot << 8) | (jj ^ (jj >> 4));
        tw3[phys] = __ldg(&W[(jj << (14 - u)) + (c << (22 - u))]);
    }

    // round 1: bits q[10:7], S0=0, jj=0
#pragma unroll
    for (int pass = 0; pass < 2; pass++) {
        unsigned low7 = rest + 64u * pass;
        float2 a[16];
#pragma unroll
        for (int x = 0; x < 16; x++)
            a[x] = make_float2(
                __ldg(&Xr[base + ((((unsigned)x << 7) | low7) << 12)]), 0.0f);
        bnet_pf<0, 4>(a, 0u, W);
#pragma unroll
        for (int x = 0; x < 16; x++)
            sm2[phA(((unsigned)x << 7) | low7, g)] = a[x];
    }
    __syncthreads();

    // round 2: bits q[6:3], S0=4, jj = brev4(q[10:7])
#pragma unroll
    for (int pass = 0; pass < 2; pass++) {
        unsigned idx2 = rest + 64u * pass;
        unsigned lo3 = idx2 & 7u;
        unsigned H = idx2 >> 3;
        unsigned jj = __brev(H) >> 28;
        float2 a[16];
#pragma unroll
        for (int x = 0; x < 16; x++)
            a[x] = sm2[phA((H << 7) | ((unsigned)x << 3) | lo3, g)];
        bnet_tw<4, 16>(a, tw2 + jj);
#pragma unroll
        for (int x = 0; x < 16; x++)
            sm2[phA((H << 7) | ((unsigned)x << 3) | lo3, g)] = a[x];
    }
    __syncthreads();

    // round 3: bits q[2:0], S0=8, jj = brev8(q[10:3]); write transposed
#pragma unroll
    for (int pass = 0; pass < 4; pass++) {
        unsigned B = rest + 64u * pass;
        unsigned jj = __brev(B) >> 24;
        float2 a[8];
#pragma unroll
        for (int x = 0; x < 8; x++)
            a[x] = sm2[phA((B << 3) | (unsigned)x, g)];
        bnet_tw<3, 256>(a, tw3 + (jj ^ (jj >> 4)));
#pragma unroll
        for (int x = 0; x < 8; x++) {
            unsigned C = ((unsigned)brev_c(x, 3) << 8) | jj;
            Yt[C * 4096u + base] = a[x];
        }
    }
}

// ============================================================================
// k2: stages [11,15). Tile = 32 i x 16 j. Loads coalesced from transpose,
// twiddles warp-uniform (lanes=i), smem exchange -> stores contiguous in j.
// Out[(i<<15) + (brev4(x)<<11) + j]  (natural layout for k3).
// ============================================================================
#define K2_SMEM_BYTES (8192 * 8)

__global__ void __launch_bounds__(512, 1)
fft_k2(const float2* __restrict__ In, const float2* __restrict__ W,
       float2* __restrict__ Out) {
    extern __shared__ float2 sE[];      // [(c<<9) | (jl<<5) | (il^jl)]
    const unsigned t = threadIdx.x;
    const unsigned bi = blockIdx.x >> 7;      // 0..7
    const unsigned bj = blockIdx.x & 127u;    // 0..127
    const unsigned I0 = bi << 5;
    const unsigned Jb = bj << 4;

    {
        const unsigned il = t & 31u;
        const unsigned jl = t >> 5;           // 0..15 (warp-uniform)
        const unsigned j = Jb + jl;
        float2 a[16];
#pragma unroll
        for (int r = 0; r < 16; r++)
            a[r] = __ldg(&In[j * 4096u + I0 + il + 256u * (unsigned)r]);
        bnet_pf<11, 4>(a, j, W);
#pragma unroll
        for (int x = 0; x < 16; x++) {
            unsigned c = (unsigned)brev_c(x, 4);
            sE[(c << 9) | (jl << 5) | (il ^ jl)] = a[x];
        }
    }
    __syncthreads();
    {
        const unsigned jl = t & 15u;
        const unsigned zz = t >> 4;           // 0..31
        const unsigned i = I0 + zz;
        const unsigned j = Jb + jl;
#pragma unroll
        for (int c = 0; c < 16; c++) {
            float2 v = sE[((unsigned)c << 9) | (jl << 5) | (zz ^ jl)];
            Out[(i << 15) + ((unsigned)c << 11) + j] = v;
        }
    }
}

// ============================================================================
// k3: stages [15,23), IN-PLACE on d_out. Tile = 64 j15 x 256 Q. Rounds 4+4.
// Round-A twiddles staged in smem; all gmem streams 256B-coalesced.
// Out[(brev8(Q)<<15) + j15].
// ============================================================================
#define K3_SMEM_BYTES ((960 + 16384) * 8)

__global__ void __launch_bounds__(512, 1)
fft_k3(float2* __restrict__ Data, const float2* __restrict__ W) {
    extern __shared__ float2 sm[];
    float2* twA = sm;                    // [slot*64 + jl], 15x64
    float2* sD = sm + 960;               // [(Q<<6) | jl]
    const unsigned t = threadIdx.x;
    const unsigned J0 = blockIdx.x << 6;
    const unsigned jl = t & 63u;
    const unsigned qh = t >> 6;          // 0..7

    // stage round-A twiddles: S0=15 -> shift 7-u
    for (unsigned e = t; e < 960; e += 512) {
        unsigned slot = e >> 6, je = e & 63u;
        unsigned u = 31 - __clz(slot + 1);
        unsigned c = slot + 1 - (1u << u);
        twA[e] = __ldg(&W[((J0 + je) << (7 - u)) + (c << (22 - u))]);
    }

    // round A: bits Q[7:4], jj = j15; all loads precede all stores (in-place ok)
    float2 a0[16], a1[16];
#pragma unroll
    for (int x = 0; x < 16; x++)
        a0[x] = __ldg(&Data[((((unsigned)x << 4) | qh) << 15) + J0 + jl]);
#pragma unroll
    for (int x = 0; x < 16; x++)
        a1[x] = __ldg(&Data[((((unsigned)x << 4) | (qh + 8u)) << 15) + J0 + jl]);
    __syncthreads();                     // twA ready
    bnet_tw<4, 64>(a0, twA + jl);
    bnet_tw<4, 64>(a1, twA + jl);
#pragma unroll
    for (int x = 0; x < 16; x++) {
        sD[((((unsigned)x << 4) | qh) << 6) | jl] = a0[x];
        sD[((((unsigned)x << 4) | (qh + 8u)) << 6) | jl] = a1[x];
    }
    __syncthreads();

    // round B: bits Q[3:0], jj = j15 + brev4(X)<<15; coalesced stores
#pragma unroll
    for (int pass = 0; pass < 2; pass++) {
        unsigned X2 = qh + 8u * pass;
        unsigned XR = __brev(X2) >> 28;
        unsigned jj = (J0 + jl) + (XR << 15);
        float2 b[16];
#pragma unroll
        for (int x = 0; x < 16; x++)
            b[x] = sD[(((X2 << 4) | (unsigned)x) << 6) | jl];
        bnet_pf<19, 4>(b, jj, W);
#pragma unroll
        for (int x = 0; x < 16; x++) {
            unsigned C = ((unsigned)brev_c(x, 4) << 4) | XR;
            Data[(C << 15) + J0 + jl] = b[x];
        }
    }
}

// ---------------------------------------------------------------------------
extern "C" void kernel_launch(void* const* d_in, const int* in_sizes, int n_in,
                              void* d_out, int out_size) {
    const float* inp = (const float*)d_in[0];
    const float2* w = (const float2*)d_in[1];
    float2* out = (float2*)d_out;

    float2* scr = nullptr;
    cudaGetSymbolAddress((void**)&scr, g_scratch);

    cudaFuncSetAttribute(fft_k1, cudaFuncAttributeMaxDynamicSharedMemorySize,
                         K1_SMEM_BYTES);
    cudaFuncSetAttribute(fft_k2, cudaFuncAttributeMaxDynamicSharedMemorySize,
                         K2_SMEM_BYTES);
    cudaFuncSetAttribute(fft_k3, cudaFuncAttributeMaxDynamicSharedMemorySize,
                         K3_SMEM_BYTES);

    fft_k1<<<512, 512, K1_SMEM_BYTES>>>(inp, w, scr);    // stages 0..10
    fft_k2<<<1024, 512, K2_SMEM_BYTES>>>(scr, w, out);   // stages 11..14
    fft_k3<<<512, 512, K3_SMEM_BYTES>>>(out, w);         // stages 15..22 in-place
}

// round 8
// speedup vs baseline: 1.0619x; 1.0619x over previous
#include <cuda_runtime.h>
#include <cuda_bf16.h>
#include <cstdint>

#define N_TOTAL 8388608   // 2^23

__device__ float2 g_scratch[N_TOTAL];   // transposed intermediate

using u64 = unsigned long long;

__host__ __device__ __forceinline__ constexpr int brev_c(int x, int K) {
    int r = 0;
    for (int b = 0; b < K; b++) r |= ((x >> b) & 1) << (K - 1 - b);
    return r;
}

// ---- packed f32x2 helpers -------------------------------------------------
__device__ __forceinline__ u64 f2_pack(float lo, float hi) {
    u64 r; asm("mov.b64 %0,{%1,%2};" : "=l"(r) : "f"(lo), "f"(hi)); return r;
}
__device__ __forceinline__ u64 f2_swap(u64 a) {
    float lo, hi;
    asm("mov.b64 {%0,%1},%2;" : "=f"(lo), "=f"(hi) : "l"(a));
    u64 r; asm("mov.b64 %0,{%1,%2};" : "=l"(r) : "f"(hi), "f"(lo)); return r;
}
__device__ __forceinline__ u64 f2_mul(u64 a, u64 b) {
    u64 r; asm("mul.rn.f32x2 %0,%1,%2;" : "=l"(r) : "l"(a), "l"(b)); return r;
}
__device__ __forceinline__ u64 f2_fma(u64 a, u64 b, u64 c) {
    u64 r; asm("fma.rn.f32x2 %0,%1,%2,%3;" : "=l"(r) : "l"(a), "l"(b), "l"(c)); return r;
}
__device__ __forceinline__ u64 f2_add(u64 a, u64 b) {
    u64 r; asm("add.rn.f32x2 %0,%1,%2;" : "=l"(r) : "l"(a), "l"(b)); return r;
}

// butterfly: a1' = a1 + w*a2 ; a2' = a1 - w*a2  (complex, packed)
__device__ __forceinline__ void bfly(u64& a1, u64& a2, u64 w1, u64 w2, u64 n1) {
    u64 p = f2_fma(f2_swap(a2), w2, f2_mul(a2, w1));
    u64 d = f2_fma(p, n1, a1);
    a1 = f2_add(a1, p);
    a2 = d;
}

// In-register DIF butterfly network, K stages at global stage offset S0,
// twiddles prefetched up front; packed f32x2 math.
template <int S0, int K>
__device__ __forceinline__ void bnet_pf(u64* a, unsigned jj,
                                        const float2* __restrict__ W) {
    float2 tw[(1 << K) - 1];
#pragma unroll
    for (int u = 0; u < K; u++) {
#pragma unroll
        for (int c = 0; c < (1 << u); c++) {
            unsigned idx = (jj << (22 - S0 - u)) + ((unsigned)c << (22 - u));
            tw[(1 << u) - 1 + c] = __ldg(&W[idx]);
        }
    }
    const u64 n1 = f2_pack(-1.0f, -1.0f);
#pragma unroll
    for (int u = 0; u < K; u++) {
        const int half = 1 << (K - 1 - u);
#pragma unroll
        for (int c = 0; c < (1 << u); c++) {
            float2 w = tw[(1 << u) - 1 + c];
            u64 w1 = f2_pack(w.x, w.x);
            u64 w2 = f2_pack(-w.y, w.y);
#pragma unroll
            for (int t = 0; t < (1 << K) / 2; t++) {
                const int q1 = ((t & ~(half - 1)) << 1) | (t & (half - 1));
                const int cc = brev_c(q1, K) & ((1 << u) - 1);
                if (cc == c) bfly(a[q1], a[q1 + half], w1, w2, n1);
            }
        }
    }
}

#define SMEM_ELEMS 16384
#define SMEM_BYTES (SMEM_ELEMS * 8)

// ============================================================================
// Kernel A: stages [0,11). Tile = 8 bases (g) x 2048 q. Rounds 4+4+3.
// u64 smem, XOR swizzle. Output transposed: Yt[brev11(q)*4096 + base].
// ============================================================================
__device__ __forceinline__ unsigned phA(unsigned q, unsigned g) {
    unsigned l = (q << 3) | g;
    return l ^ (((l >> 6) & 1u) << 3);
}

__global__ void __launch_bounds__(512, 1)
fft_kA(const float* __restrict__ Xr, const float2* __restrict__ W,
       float2* __restrict__ Yt) {
    extern __shared__ u64 sm2[];
    u64* Yo = reinterpret_cast<u64*>(Yt);

    const unsigned t = threadIdx.x;
    const unsigned g = t & 7u;
    const unsigned rest = t >> 3;              // 0..63
    const unsigned base = blockIdx.x * 8u + g;

    // round 1: bits q[10:7], S0=0, jj=0 (gmem load, imag=0)
#pragma unroll
    for (int pass = 0; pass < 2; pass++) {
        unsigned low7 = rest + 64u * pass;     // q[6:0]
        u64 a[16];
#pragma unroll
        for (int x = 0; x < 16; x++)
            a[x] = f2_pack(
                __ldg(&Xr[base + ((((unsigned)x << 7) | low7) << 12)]), 0.0f);
        bnet_pf<0, 4>(a, 0u, W);
#pragma unroll
        for (int x = 0; x < 16; x++)
            sm2[phA(((unsigned)x << 7) | low7, g)] = a[x];
    }
    __syncthreads();

    // round 2: bits q[6:3], S0=4, jj = brev4(q[10:7])
#pragma unroll
    for (int pass = 0; pass < 2; pass++) {
        unsigned idx2 = rest + 64u * pass;     // 0..127
        unsigned lo3 = idx2 & 7u;              // q[2:0]
        unsigned H = idx2 >> 3;                // q[10:7]
        unsigned jj = __brev(H) >> 28;
        u64 a[16];
#pragma unroll
        for (int x = 0; x < 16; x++)
            a[x] = sm2[phA((H << 7) | ((unsigned)x << 3) | lo3, g)];
        bnet_pf<4, 4>(a, jj, W);
#pragma unroll
        for (int x = 0; x < 16; x++)
            sm2[phA((H << 7) | ((unsigned)x << 3) | lo3, g)] = a[x];
    }
    __syncthreads();

    // round 3: bits q[2:0], S0=8, K=3, jj = brev8(q[10:3]); write transposed
#pragma unroll
    for (int pass = 0; pass < 4; pass++) {
        unsigned B = rest + 64u * pass;        // q[10:3], 0..255
        unsigned jj = __brev(B) >> 24;
        u64 a[8];
#pragma unroll
        for (int x = 0; x < 8; x++)
            a[x] = sm2[phA((B << 3) | (unsigned)x, g)];
        bnet_pf<8, 3>(a, jj, W);
#pragma unroll
        for (int x = 0; x < 8; x++) {
            unsigned C = ((unsigned)brev_c(x, 3) << 8) | jj;  // brev11(q)
            Yo[C * 4096u + base] = a[x];
        }
    }
}

// ============================================================================
// Kernel B: stages [11,23). Tile = 4 j x 4096 q. Rounds 4+4+4.
// Round 1 lane map: 32 consecutive q per warp, single jB -> coalesced loads +
// warp-uniform twiddles. u64 smem + XOR swizzle.
// Output: Out[(brev12(q) << 11) + j].
// ============================================================================
__device__ __forceinline__ unsigned phB(unsigned q, unsigned js) {
    unsigned l = (q << 2) | js;
    return l ^ ((l >> 4) & 3u) ^ (((l >> 6) & 3u) << 2);
}

__global__ void __launch_bounds__(512, 1)
fft_kB(const float2* __restrict__ In, const float2* __restrict__ W,
       float2* __restrict__ Out) {
    extern __shared__ u64 sm2[];
    const u64* Ii = reinterpret_cast<const u64*>(In);
    u64* Oo = reinterpret_cast<u64*>(Out);

    const unsigned t = threadIdx.x;
    const unsigned j0 = blockIdx.x * 4u;

    // round 1: bits q[11:8], S0=11. jg1 = t>>7 (warp-uniform jB).
    {
        const unsigned jg1 = t >> 7;           // 0..3
        const unsigned lowt = t & 127u;
        const unsigned jB1 = j0 + jg1;
#pragma unroll
        for (int pass = 0; pass < 2; pass++) {
            unsigned low8 = lowt + 128u * pass;  // q[7:0]
            u64 a[16];
#pragma unroll
            for (int x = 0; x < 16; x++)
                a[x] = Ii[jB1 * 4096u + (((unsigned)x << 8) | low8)];
            bnet_pf<11, 4>(a, jB1, W);
#pragma unroll
            for (int x = 0; x < 16; x++) {
                unsigned q = ((unsigned)x << 8) | low8;
                sm2[phB(q, jg1)] = a[x];
            }
        }
    }
    __syncthreads();

    const unsigned jg = t & 3u;
    const unsigned rest = t >> 2;              // 0..127
    const unsigned jB = j0 + jg;

    // round 2: bits q[7:4], S0=15, jj = jB + brev4(q[11:8])<<11
#pragma unroll
    for (int pass = 0; pass < 2; pass++) {
        unsigned idx2 = rest + 128u * pass;    // 0..255
        unsigned lo4 = idx2 & 15u;             // q[3:0]
        unsigned H = idx2 >> 4;                // q[11:8]
        unsigned jj = jB + ((__brev(H) >> 28) << 11);
        u64 a[16];
#pragma unroll
        for (int x = 0; x < 16; x++)
            a[x] = sm2[phB((H << 8) | ((unsigned)x << 4) | lo4, jg)];
        bnet_pf<15, 4>(a, jj, W);
#pragma unroll
        for (int x = 0; x < 16; x++)
            sm2[phB((H << 8) | ((unsigned)x << 4) | lo4, jg)] = a[x];
    }
    __syncthreads();

    // round 3: bits q[3:0], S0=19, jj = jB + brev8(q[11:4])<<11; write out
#pragma unroll
    for (int pass = 0; pass < 2; pass++) {
        unsigned B = rest + 128u * pass;       // q[11:4], 0..255
        unsigned Brev = __brev(B) >> 24;
        unsigned jj = jB + (Brev << 11);
        u64 a[16];
#pragma unroll
        for (int x = 0; x < 16; x++)
            a[x] = sm2[phB((B << 4) | (unsigned)x, jg)];
        bnet_pf<19, 4>(a, jj, W);
#pragma unroll
        for (int x = 0; x < 16; x++) {
            unsigned C = ((unsigned)brev_c(x, 4) << 8) | Brev;  // brev12(q)
            Oo[(C << 11) + jB] = a[x];
        }
    }
}

// ---------------------------------------------------------------------------
extern "C" void kernel_launch(void* const* d_in, const int* in_sizes, int n_in,
                              void* d_out, int out_size) {
    const float* inp = (const float*)d_in[0];
    const float2* w = (const float2*)d_in[1];
    float2* out = (float2*)d_out;

    float2* scr = nullptr;
    cudaGetSymbolAddress((void**)&scr, g_scratch);

    cudaFuncSetAttribute(fft_kA, cudaFuncAttributeMaxDynamicSharedMemorySize,
                         SMEM_BYTES);
    cudaFuncSetAttribute(fft_kB, cudaFuncAttributeMaxDynamicSharedMemorySize,
                         SMEM_BYTES);

    fft_kA<<<512, 512, SMEM_BYTES>>>(inp, w, scr);   // stages 0..10
    fft_kB<<<512, 512, SMEM_BYTES>>>(scr, w, out);   // stages 11..22
}